// round 8
// baseline (speedup 1.0000x reference)
#include <cuda_runtime.h>
#include <math.h>
#include <stdint.h>

#define S_LEN 2048
#define B_SZ  64
#define E_SZ  256
#define H_SZ  256

// Scratch for x_proj: [S, B, H] fp32 = 134 MB
__device__ float g_xproj[(size_t)S_LEN * B_SZ * H_SZ];

typedef unsigned long long ull;

// ---- packed f32x2 helpers ---------------------------------------------------
__device__ __forceinline__ ull fma2(ull a, ull b, ull c) {
    ull d;
    asm("fma.rn.f32x2 %0, %1, %2, %3;" : "=l"(d) : "l"(a), "l"(b), "l"(c));
    return d;
}
__device__ __forceinline__ ull pack2(float lo, float hi) {
    ull d;
    asm("mov.b64 %0, {%1, %2};" : "=l"(d) : "f"(lo), "f"(hi));
    return d;
}
__device__ __forceinline__ void unpack2(ull v, float& lo, float& hi) {
    asm("mov.b64 {%0, %1}, %2;" : "=f"(lo), "=f"(hi) : "l"(v));
}

// fast tanh: tanh(x) = 1 - 2/(exp(2x)+1), via MUFU.EX2 + MUFU.RCP (~1e-6 err)
__device__ __forceinline__ float fast_tanh(float x) {
    float u, r;
    asm("ex2.approx.f32 %0, %1;" : "=f"(u) : "f"(x * 2.885390082f));
    asm("rcp.approx.f32 %0, %1;" : "=f"(r) : "f"(u + 1.0f));
    return fmaf(-2.0f, r, 1.0f);
}

// ---- cluster / mbarrier helpers --------------------------------------------
__device__ __forceinline__ uint32_t smem_u32(const void* p) {
    uint32_t a;
    asm("{ .reg .u64 t; cvta.to.shared.u64 t, %1; cvt.u32.u64 %0, t; }"
        : "=r"(a) : "l"(p));
    return a;
}
__device__ __forceinline__ uint32_t ctarank() {
    uint32_t r;
    asm("mov.u32 %0, %%cluster_ctarank;" : "=r"(r));
    return r;
}
__device__ __forceinline__ uint32_t mapa_cluster(uint32_t addr, uint32_t rank) {
    uint32_t r;
    asm("mapa.shared::cluster.u32 %0, %1, %2;" : "=r"(r) : "r"(addr), "r"(rank));
    return r;
}
__device__ __forceinline__ void st_async32(uint32_t raddr, float v, uint32_t rmbar) {
    asm volatile(
        "st.async.shared::cluster.mbarrier::complete_tx::bytes.b32 [%0], %1, [%2];"
        :: "r"(raddr), "r"(__float_as_uint(v)), "r"(rmbar) : "memory");
}
__device__ __forceinline__ void mbar_init(uint32_t mbar, uint32_t count) {
    asm volatile("mbarrier.init.shared.b64 [%0], %1;"
                 :: "r"(mbar), "r"(count) : "memory");
}
__device__ __forceinline__ void mbar_arrive_expect_tx(uint32_t mbar, uint32_t bytes) {
    asm volatile("mbarrier.arrive.expect_tx.shared.b64 _, [%0], %1;"
                 :: "r"(mbar), "r"(bytes) : "memory");
}
// CTA-scope acquire: barrier AND payload live in LOCAL smem (st.async lands
// here); cta scope avoids the cluster-scope L1-flush path.
__device__ __forceinline__ void mbar_wait_cta(uint32_t mbar, uint32_t parity) {
    uint32_t done;
    asm volatile(
        "{\n\t"
        ".reg .pred p;\n\t"
        "mbarrier.try_wait.parity.acquire.cta.shared::cta.b64 p, [%1], %2;\n\t"
        "selp.b32 %0, 1, 0, p;\n\t"
        "}"
        : "=r"(done) : "r"(mbar), "r"(parity) : "memory");
    if (!done) {
        asm volatile(
            "{\n\t"
            ".reg .pred P1;\n\t"
            "WAIT_LOOP_%=:\n\t"
            "mbarrier.try_wait.parity.acquire.cta.shared::cta.b64 P1, [%0], %1, 0x989680;\n\t"
            "@P1 bra.uni WAIT_DONE_%=;\n\t"
            "bra.uni WAIT_LOOP_%=;\n\t"
            "WAIT_DONE_%=:\n\t"
            "}"
            :: "r"(mbar), "r"(parity) : "memory");
    }
}
__device__ __forceinline__ void cluster_sync_all() {
    asm volatile("barrier.cluster.arrive.aligned;" ::: "memory");
    asm volatile("barrier.cluster.wait.aligned;" ::: "memory");
}

// ---------------------------------------------------------------------------
// Kernel 1: x_proj = sentence @ W_ih + b  (R4 version — measured ~393us)
// ---------------------------------------------------------------------------
__global__ __launch_bounds__(256) void xproj_kernel(
    const float* __restrict__ sent,
    const float* __restrict__ Wih,
    const float* __restrict__ bias)
{
    __shared__ float xs[8][256];
    __shared__ float part[4][8][256];

    const int t  = threadIdx.x;
    const int m0 = blockIdx.x * 8;

    {
        const float4* srow = (const float4*)(sent + (size_t)m0 * 256);
        float4* xs4 = (float4*)&xs[0][0];
        #pragma unroll
        for (int i = 0; i < 2; i++)
            xs4[t + i * 256] = srow[t + i * 256];
    }
    __syncthreads();

    const int jg = t & 63;
    const int ks = t >> 6;
    const float4* W4 = (const float4*)Wih;

    float4 acc[8];
    #pragma unroll
    for (int r = 0; r < 8; r++) acc[r] = make_float4(0.f, 0.f, 0.f, 0.f);

    #pragma unroll 8
    for (int i = 0; i < 64; i++) {
        const int k = ks * 64 + i;
        const float4 w = W4[k * 64 + jg];
        #pragma unroll
        for (int r = 0; r < 8; r++) {
            const float xv = xs[r][k];
            acc[r].x += xv * w.x;
            acc[r].y += xv * w.y;
            acc[r].z += xv * w.z;
            acc[r].w += xv * w.w;
        }
    }

    #pragma unroll
    for (int r = 0; r < 8; r++)
        *(float4*)&part[ks][r][4 * jg] = acc[r];
    __syncthreads();

    const float bj = bias[t];
    #pragma unroll
    for (int r = 0; r < 8; r++) {
        const float v = part[0][r][t] + part[1][r][t] +
                        part[2][r][t] + part[3][r][t] + bj;
        g_xproj[(size_t)(m0 + r) * 256 + t] = v;
    }
}

// ---------------------------------------------------------------------------
// Kernel 2: the scan. 2-CTA cluster per batch row (128 CTAs), 256 threads.
// CTA rank r owns output cols [128r, 128r+128). Thread pair (2c, 2c+1) owns
// col c: kh = t&1 selects which 64-k half of the dot product the thread does.
// W: fully register-resident (64 ull = 128 regs/thread). h in SMEM, pair-
// packed, PADDED layout (32-pair blocks, stride 68 floats) so the two kh
// halves hit disjoint banks. Own-k FMAs run before the peer wait (hides the
// DSMEM delivery); pair reduced via shfl.xor; 128 st.async.b32/step to peer.
// ---------------------------------------------------------------------------
#define HBLK 68   // floats per 32-pair block (64 data + 4 pad)

__global__ __launch_bounds__(256, 1) __cluster_dims__(2, 1, 1)
void scan_kernel(
    const float* __restrict__ Whh,    // [256,256] row-major (k, j)
    const float* __restrict__ h0,     // [64,256]
    float* __restrict__ out)          // [64,256]
{
    __shared__ __align__(16) float hsh[2][8 * HBLK];   // 2 x 2176 B
    __shared__ __align__(8)  ull   mbar_store[2];

    const int t     = threadIdx.x;
    const int b     = blockIdx.x >> 1;
    const uint32_t rank  = ctarank();
    const uint32_t prank = rank ^ 1u;
    const int cloc  = t >> 1;                 // 0..127 local column
    const int kh    = t & 1;                  // which k-half of the dot
    const int gc    = (int)rank * 128 + cloc; // global column

    // k-pair ranges (pair P covers k = 2P, 2P+1). Own = this CTA's cols.
    const int Po = 64 * (int)rank  + 32 * kh;   // 32 own pairs
    const int Pp = 64 * (int)prank + 32 * kh;   // 32 peer pairs

    // ---- one-time: fully register-resident W (64 pairs x 1 col) ----
    ull wo[32], wp[32];
    #pragma unroll
    for (int i = 0; i < 32; i++) {
        const int k = 2 * (Po + i);
        wo[i] = pack2(Whh[(size_t)k * 256 + gc], Whh[(size_t)(k + 1) * 256 + gc]);
    }
    #pragma unroll
    for (int i = 0; i < 32; i++) {
        const int k = 2 * (Pp + i);
        wp[i] = pack2(Whh[(size_t)k * 256 + gc], Whh[(size_t)(k + 1) * 256 + gc]);
    }

    // ---- init h buffer 0 (padded layout) ----
    {
        const int j = t;                       // element index 0..255
        const int P = j >> 1;
        const int addr = (P >> 5) * HBLK + (P & 31) * 2 + (j & 1);
        hsh[0][addr] = h0[(size_t)b * 256 + j];
    }
    const uint32_t mb0 = smem_u32(&mbar_store[0]);
    const uint32_t mb1 = smem_u32(&mbar_store[1]);
    if (t == 0) { mbar_init(mb0, 1); mbar_init(mb1, 1); }
    __syncthreads();
    cluster_sync_all();     // peer mbarriers + hsh live before any st.async

    // peer-side addresses
    const uint32_t peer_h0  = mapa_cluster(smem_u32(&hsh[0][0]), prank);
    const uint32_t peer_h1  = mapa_cluster(smem_u32(&hsh[1][0]), prank);
    const uint32_t peer_mb0 = mapa_cluster(mb0, prank);
    const uint32_t peer_mb1 = mapa_cluster(mb1, prank);

    const int own_base_f  = (Po >> 5) * HBLK;  // float offset of own block
    const int peer_base_f = (Pp >> 5) * HBLK;

    // write address (even lanes): element gc in padded layout
    const int wP    = gc >> 1;
    const int waddr = (wP >> 5) * HBLK + (wP & 31) * 2 + (gc & 1);

    float xcur = 0.f, xnext = 0.f, hlast = 0.f;
    if (kh == 0)
        xcur = g_xproj[((size_t)0 * B_SZ + b) * 256 + gc];

    for (int s = 0; s < S_LEN; s++) {
        const int mnext = (s + 1) & 1;
        const uint32_t my_mb_next   = mnext ? mb1 : mb0;
        const uint32_t peer_mb_next = mnext ? peer_mb1 : peer_mb0;
        const uint32_t peer_h_next  = mnext ? peer_h1 : peer_h0;

        // arm my barrier for the peer's h_{s+1} bytes (128 x 4B)
        if (t == 0) mbar_arrive_expect_tx(my_mb_next, 512);

        if (kh == 0) {
            const int sn = (s + 1 < S_LEN) ? s + 1 : s;
            xnext = g_xproj[((size_t)sn * B_SZ + b) * 256 + gc];
        }

        const float* hcur = hsh[s & 1];

        // ---- own-half FMAs (local h — no wait) ----
        ull acc0 = 0, acc1 = 0;
        {
            const ulonglong2* ho = (const ulonglong2*)(hcur + own_base_f);
            #pragma unroll
            for (int i = 0; i < 16; i++) {
                const ulonglong2 hv = ho[i];
                acc0 = fma2(wo[2 * i],     hv.x, acc0);
                acc1 = fma2(wo[2 * i + 1], hv.y, acc1);
            }
        }

        // ---- wait for peer's half of h_s (delivery overlapped above) ----
        if (s > 0) {
            const uint32_t my_mb_cur = (s & 1) ? mb1 : mb0;
            mbar_wait_cta(my_mb_cur, (uint32_t)(((s - 1) >> 1) & 1));
        }

        // ---- peer-half FMAs ----
        {
            const ulonglong2* hp = (const ulonglong2*)(hcur + peer_base_f);
            #pragma unroll
            for (int i = 0; i < 16; i++) {
                const ulonglong2 hv = hp[i];
                acc0 = fma2(wp[2 * i],     hv.x, acc0);
                acc1 = fma2(wp[2 * i + 1], hv.y, acc1);
            }
        }

        // ---- pair reduce + tanh + store/send (even lanes) ----
        float s0, s1, s2, s3;
        unpack2(acc0, s0, s1);
        unpack2(acc1, s2, s3);
        float vh = (s0 + s1) + (s2 + s3);
        vh += __shfl_xor_sync(0xffffffffu, vh, 1);

        if (kh == 0) {
            const float h = fast_tanh(vh + xcur);
            hlast = h;
            hsh[mnext][waddr] = h;                              // local copy
            st_async32(peer_h_next + (uint32_t)waddr * 4, h,    // peer copy
                       peer_mb_next);
            xcur = xnext;
        }
        __syncthreads();    // local h_{s+1} writes visible to all warps
    }

    if (kh == 0)
        out[(size_t)b * 256 + gc] = hlast;

    cluster_sync_all();     // don't exit while peer st.async may be in flight
}

// ---------------------------------------------------------------------------
extern "C" void kernel_launch(void* const* d_in, const int* in_sizes, int n_in,
                              void* d_out, int out_size)
{
    const float* sentence = (const float*)d_in[0];
    const float* h0       = (const float*)d_in[1];
    const float* W_ih     = (const float*)d_in[2];
    const float* W_hh     = (const float*)d_in[3];
    const float* bias     = (const float*)d_in[4];
    float* out = (float*)d_out;

    (void)in_sizes; (void)n_in; (void)out_size;

    xproj_kernel<<<(S_LEN * B_SZ) / 8, 256>>>(sentence, W_ih, bias);

    scan_kernel<<<2 * B_SZ, 256>>>(W_hh, h0, out);
}

// round 9
// speedup vs baseline: 1.0341x; 1.0341x over previous
#include <cuda_runtime.h>
#include <math.h>
#include <stdint.h>

#define S_LEN 2048
#define B_SZ  64
#define E_SZ  256
#define H_SZ  256

// Scratch for x_proj: [S, B, H] fp32 = 134 MB
__device__ float g_xproj[(size_t)S_LEN * B_SZ * H_SZ];

typedef unsigned long long ull;

// ---- packed f32x2 helpers ---------------------------------------------------
__device__ __forceinline__ ull fma2(ull a, ull b, ull c) {
    ull d;
    asm("fma.rn.f32x2 %0, %1, %2, %3;" : "=l"(d) : "l"(a), "l"(b), "l"(c));
    return d;
}
__device__ __forceinline__ ull add2(ull a, ull b) {
    ull d;
    asm("add.rn.f32x2 %0, %1, %2;" : "=l"(d) : "l"(a), "l"(b));
    return d;
}
__device__ __forceinline__ ull pack2(float lo, float hi) {
    ull d;
    asm("mov.b64 %0, {%1, %2};" : "=l"(d) : "f"(lo), "f"(hi));
    return d;
}
__device__ __forceinline__ void unpack2(ull v, float& lo, float& hi) {
    asm("mov.b64 {%0, %1}, %2;" : "=f"(lo), "=f"(hi) : "l"(v));
}

// fast tanh: tanh(x) = 1 - 2/(exp(2x)+1), via MUFU.EX2 + MUFU.RCP (~1e-6 err)
__device__ __forceinline__ float fast_tanh(float x) {
    float u, r;
    asm("ex2.approx.f32 %0, %1;" : "=f"(u) : "f"(x * 2.885390082f));
    asm("rcp.approx.f32 %0, %1;" : "=f"(r) : "f"(u + 1.0f));
    return fmaf(-2.0f, r, 1.0f);
}

// 64-bit packed-float butterfly step: shfl both halves, f32x2 add
__device__ __forceinline__ ull bfly2(ull a, int m) {
    const ull o = __shfl_xor_sync(0xffffffffu, a, m);
    return add2(a, o);
}

// ---------------------------------------------------------------------------
// Kernel 1: x_proj = sentence @ W_ih + b  (R4 version — measured ~393us)
// ---------------------------------------------------------------------------
__global__ __launch_bounds__(256) void xproj_kernel(
    const float* __restrict__ sent,
    const float* __restrict__ Wih,
    const float* __restrict__ bias)
{
    __shared__ float xs[8][256];
    __shared__ float part[4][8][256];

    const int t  = threadIdx.x;
    const int m0 = blockIdx.x * 8;

    {
        const float4* srow = (const float4*)(sent + (size_t)m0 * 256);
        float4* xs4 = (float4*)&xs[0][0];
        #pragma unroll
        for (int i = 0; i < 2; i++)
            xs4[t + i * 256] = srow[t + i * 256];
    }
    __syncthreads();

    const int jg = t & 63;
    const int ks = t >> 6;
    const float4* W4 = (const float4*)Wih;

    float4 acc[8];
    #pragma unroll
    for (int r = 0; r < 8; r++) acc[r] = make_float4(0.f, 0.f, 0.f, 0.f);

    #pragma unroll 8
    for (int i = 0; i < 64; i++) {
        const int k = ks * 64 + i;
        const float4 w = W4[k * 64 + jg];
        #pragma unroll
        for (int r = 0; r < 8; r++) {
            const float xv = xs[r][k];
            acc[r].x += xv * w.x;
            acc[r].y += xv * w.y;
            acc[r].z += xv * w.z;
            acc[r].w += xv * w.w;
        }
    }

    #pragma unroll
    for (int r = 0; r < 8; r++)
        *(float4*)&part[ks][r][4 * jg] = acc[r];
    __syncthreads();

    const float bj = bias[t];
    #pragma unroll
    for (int r = 0; r < 8; r++) {
        const float v = part[0][r][t] + part[1][r][t] +
                        part[2][r][t] + part[3][r][t] + bj;
        g_xproj[(size_t)(m0 + r) * 256 + t] = v;
    }
}

// ---------------------------------------------------------------------------
// Kernel 2: the scan. 64 CTAs (1 batch row), 256 threads, ONE BAR per step.
// Lane decomposition (warp w = t>>5, lane = t&31):
//   cg = lane & 3   -> 8-column group: base = w*32 + cg*8
//   kk = lane >> 2  -> 8-way k-split over INTERLEAVED k: k in {kk + 8i}
// W: 26 i's register-resident (104 ull), 6 i's in SMEM (48 KB).
// h: replicated (h,h) ull, DOUBLE-BUFFERED -> no WAR hazard -> 1 BAR/step.
// Reduction: 3-round shfl.xor butterfly over kk (f32x2 adds); every kk-lane
// then finalizes a different one of the group's 8 columns. No SMEM partials.
// ---------------------------------------------------------------------------
#define K_REG  26
#define K_SMEM 6

__global__ __launch_bounds__(256, 1) void scan_kernel(
    const float* __restrict__ Whh,    // [256,256] row-major (k, j)
    const float* __restrict__ h0,     // [64,256]
    float* __restrict__ out)          // [64,256]
{
    extern __shared__ ull smem[];
    ulonglong2* sW   = (ulonglong2*)smem;                     // [6][2][256] u2
    ull*        hbuf = smem + (size_t)K_SMEM * 2 * 256 * 2;   // [2][256] ull

    const int t    = threadIdx.x;
    const int b    = blockIdx.x;
    const int w    = t >> 5;
    const int lane = t & 31;
    const int cg   = lane & 3;
    const int kk   = lane >> 2;          // k-slot 0..7
    const int base = w * 32 + cg * 8;    // first of 8 owned columns
    const int j    = base + kk;          // column this thread finalizes

    // ---- one-time: register-resident W (26 interleaved k's x 8 cols) ----
    ull wr[4 * K_REG];
    #pragma unroll
    for (int i = 0; i < K_REG; i++) {
        const int k = kk + 8 * i;
        const ulonglong2 wa = *(const ulonglong2*)&Whh[(size_t)k * 256 + base];
        const ulonglong2 wb = *(const ulonglong2*)&Whh[(size_t)k * 256 + base + 4];
        wr[4 * i + 0] = wa.x;
        wr[4 * i + 1] = wa.y;
        wr[4 * i + 2] = wb.x;
        wr[4 * i + 3] = wb.y;
    }

    // ---- one-time: SMEM W (6 interleaved k's x 8 cols per thread) ----
    #pragma unroll
    for (int i6 = 0; i6 < K_SMEM; i6++) {
        const int k = kk + 8 * (K_REG + i6);
        sW[(i6 * 2 + 0) * 256 + t] = *(const ulonglong2*)&Whh[(size_t)k * 256 + base];
        sW[(i6 * 2 + 1) * 256 + t] = *(const ulonglong2*)&Whh[(size_t)k * 256 + base + 4];
    }

    // ---- init h buffer 0 (replicated pairs) ----
    {
        const float ha = h0[(size_t)b * 256 + t];
        hbuf[t] = pack2(ha, ha);
    }
    __syncthreads();

    float xcur = g_xproj[((size_t)0 * B_SZ + b) * 256 + j];
    float xnext;
    float hlast = 0.f;

    for (int s = 0; s < S_LEN; s++) {
        {
            const int sn = (s + 1 < S_LEN) ? s + 1 : s;
            xnext = g_xproj[((size_t)sn * B_SZ + b) * 256 + j];
        }

        const ull* hc = hbuf + (s & 1) * 256;
        ull a0 = 0, a1 = 0, a2 = 0, a3 = 0;

        // register part: k = kk + 8i, i = 0..25  (h load = 1-wavefront bcast)
        #pragma unroll
        for (int i = 0; i < K_REG; i++) {
            const ull hv = hc[kk + 8 * i];      // (h,h) replicated
            a0 = fma2(wr[4 * i + 0], hv, a0);
            a1 = fma2(wr[4 * i + 1], hv, a1);
            a2 = fma2(wr[4 * i + 2], hv, a2);
            a3 = fma2(wr[4 * i + 3], hv, a3);
        }
        // smem part: i = 26..31
        #pragma unroll
        for (int i6 = 0; i6 < K_SMEM; i6++) {
            const ull hv = hc[kk + 8 * (K_REG + i6)];
            const ulonglong2 wa = sW[(i6 * 2 + 0) * 256 + t];
            const ulonglong2 wb = sW[(i6 * 2 + 1) * 256 + t];
            a0 = fma2(wa.x, hv, a0);
            a1 = fma2(wa.y, hv, a1);
            a2 = fma2(wb.x, hv, a2);
            a3 = fma2(wb.y, hv, a3);
        }

        // ---- butterfly reduce over kk (lane bits 2,3,4), packed f32x2 ----
        a0 = bfly2(a0, 4);  a1 = bfly2(a1, 4);
        a2 = bfly2(a2, 4);  a3 = bfly2(a3, 4);
        a0 = bfly2(a0, 8);  a1 = bfly2(a1, 8);
        a2 = bfly2(a2, 8);  a3 = bfly2(a3, 8);
        a0 = bfly2(a0, 16); a1 = bfly2(a1, 16);
        a2 = bfly2(a2, 16); a3 = bfly2(a3, 16);

        // ---- finalize column j = base + kk ----
        const ull sel = (kk & 4) ? ((kk & 2) ? a3 : a2)
                                 : ((kk & 2) ? a1 : a0);
        float lo, hi;
        unpack2(sel, lo, hi);
        const float v = ((kk & 1) ? hi : lo) + xcur;
        const float h = fast_tanh(v);
        hlast = h;
        hbuf[((s + 1) & 1) * 256 + j] = pack2(h, h);
        xcur = xnext;
        __syncthreads();    // ONE barrier per step
    }

    out[(size_t)b * 256 + j] = hlast;
}

// ---------------------------------------------------------------------------
extern "C" void kernel_launch(void* const* d_in, const int* in_sizes, int n_in,
                              void* d_out, int out_size)
{
    const float* sentence = (const float*)d_in[0];
    const float* h0       = (const float*)d_in[1];
    const float* W_ih     = (const float*)d_in[2];
    const float* W_hh     = (const float*)d_in[3];
    const float* bias     = (const float*)d_in[4];
    float* out = (float*)d_out;

    (void)in_sizes; (void)n_in; (void)out_size;

    xproj_kernel<<<(S_LEN * B_SZ) / 8, 256>>>(sentence, W_ih, bias);

    const int smem_bytes = K_SMEM * 2 * 256 * 16 + 2 * 256 * 8;  // 48K + 4K
    cudaFuncSetAttribute(scan_kernel,
                         cudaFuncAttributeMaxDynamicSharedMemorySize,
                         smem_bytes);
    scan_kernel<<<B_SZ, 256, smem_bytes>>>(W_hh, h0, out);
}